// round 3
// baseline (speedup 1.0000x reference)
#include <cuda_runtime.h>

#define TT 200
#define BB 1024
#define DD 128
#define NN 384   // 3 gates * 128
#define XPAD 132 // padded k-row length for x/s tiles (conflict-free, 16B-aligned rows)

// ---------------- device scratch (no runtime allocation allowed) ----------------
// Ax layout: [chunk c][n][row r], c = (t*BB + b)/8. Written/read as float4 pairs.
__device__ float g_Ax[(size_t)TT * BB * NN];

// ---------------- f32x2 packed-FMA helpers (Blackwell dual-fp32) ----------------
static __device__ __forceinline__ unsigned long long pk2(float lo, float hi) {
    unsigned long long r;
    asm("mov.b64 %0, {%1,%2};" : "=l"(r) : "f"(lo), "f"(hi));
    return r;
}
static __device__ __forceinline__ void upk2(unsigned long long v, float &lo, float &hi) {
    asm("mov.b64 {%0,%1}, %2;" : "=f"(lo), "=f"(hi) : "l"(v));
}
static __device__ __forceinline__ unsigned long long ffma2(unsigned long long a,
                                                           unsigned long long b,
                                                           unsigned long long c) {
    unsigned long long d;
    asm("fma.rn.f32x2 %0, %1, %2, %3;" : "=l"(d) : "l"(a), "l"(b), "l"(c));
    return d;
}

static __device__ __forceinline__ float fsig(float x) {
    return __fdividef(1.f, 1.f + __expf(-x));
}
static __device__ __forceinline__ float ftanh(float x) {
    float y = fminf(fmaxf(2.f * x, -30.f), 30.f);
    float e = __expf(y);
    return __fdividef(e - 1.f, e + 1.f);
}

// Shared inner matvec: acc over k-paired weights. xr points to a 128-float row
// (16B aligned). Returns dot(w_col, row) given wp = k-paired weight column.
static __device__ __forceinline__ float dot_row(const float* __restrict__ xr,
                                                const unsigned long long* __restrict__ wp) {
    unsigned long long a0 = 0ull, a1 = 0ull;
#pragma unroll
    for (int k = 0; k < DD; k += 8) {
        ulonglong2 p0 = *(const ulonglong2*)(xr + k);
        ulonglong2 p1 = *(const ulonglong2*)(xr + k + 4);
        a0 = ffma2(p0.x, wp[k / 2 + 0], a0);
        a1 = ffma2(p0.y, wp[k / 2 + 1], a1);
        a0 = ffma2(p1.x, wp[k / 2 + 2], a0);
        a1 = ffma2(p1.y, wp[k / 2 + 3], a1);
    }
    float l0, h0, l1, h1;
    upk2(a0, l0, h0);
    upk2(a1, l1, h1);
    return (l0 + h0) + (l1 + h1);
}

// ==================== phase 1: Ax = X @ [Wau|War|Wac] + bias ====================
// Persistent: 148 CTAs loop over 8-row chunks. Thread n holds its k-paired
// weight column in 64 ull registers. X rows broadcast from smem [row][k].
__global__ __launch_bounds__(384, 1)
void xproj_kernel(const float* __restrict__ X,
                  const float* __restrict__ Wau, const float* __restrict__ bau,
                  const float* __restrict__ War, const float* __restrict__ bar,
                  const float* __restrict__ Wac, const float* __restrict__ bac) {
    __shared__ __align__(16) float x_sh[2][8][XPAD];

    const int tid = threadIdx.x;
    const int g = tid >> 7;
    const int d = tid & 127;

    const float* W = (g == 0) ? Wau : ((g == 1) ? War : Wac);
    const float* bp = (g == 0) ? bau : ((g == 1) ? bar : bac);

    unsigned long long wp[DD / 2];
#pragma unroll
    for (int i = 0; i < DD / 2; i++)
        wp[i] = pk2(W[(2 * i) * DD + d], W[(2 * i + 1) * DD + d]);
    const float bias = bp[d];

    const int NCHUNK = TT * BB / 8;   // 25600

    // prefetch chunk 0 into buf 0
    int c = blockIdx.x;
    {
        const float* p = X + (size_t)c * (8 * DD);
        float v0 = p[tid];
        float v1 = p[tid + 384];
        float v2 = (tid < 256) ? p[tid + 768] : 0.f;
        x_sh[0][tid >> 7][tid & 127] = v0;
        x_sh[0][(tid + 384) >> 7][(tid + 384) & 127] = v1;
        if (tid < 256) x_sh[0][(tid + 768) >> 7][(tid + 768) & 127] = v2;
    }
    __syncthreads();

    int buf = 0;
    for (; c < NCHUNK; c += gridDim.x) {
        const int cn = c + gridDim.x;
        float v0 = 0.f, v1 = 0.f, v2 = 0.f;
        if (cn < NCHUNK) {
            const float* p = X + (size_t)cn * (8 * DD);
            v0 = p[tid];
            v1 = p[tid + 384];
            v2 = (tid < 256) ? p[tid + 768] : 0.f;
        }

        float res[8];
#pragma unroll
        for (int r = 0; r < 8; r++)
            res[r] = dot_row(&x_sh[buf][r][0], wp) + bias;

        float* outp = g_Ax + ((size_t)c * NN + tid) * 8;
        *(float4*)(outp + 0) = make_float4(res[0], res[1], res[2], res[3]);
        *(float4*)(outp + 4) = make_float4(res[4], res[5], res[6], res[7]);

        if (cn < NCHUNK) {
            x_sh[buf ^ 1][tid >> 7][tid & 127] = v0;
            x_sh[buf ^ 1][(tid + 384) >> 7][(tid + 384) & 127] = v1;
            if (tid < 256) x_sh[buf ^ 1][(tid + 768) >> 7][(tid + 768) & 127] = v2;
        }
        __syncthreads();
        buf ^= 1;
    }
}

// ==================== phase 2: recurrence, 1 CTA = 8 batch rows ====================
// Thread n in [0,384): gate = n>>7, d = n&127. K-paired Wb column in 64 ull regs.
__global__ __launch_bounds__(384, 1)
void recur_kernel(const float* __restrict__ state0,
                  const float* __restrict__ att,    // [T,B,1]
                  const float* __restrict__ mask,   // [B,T]
                  const float* __restrict__ Wbu, const float* __restrict__ Wbr,
                  const float* __restrict__ Wbc,
                  float* __restrict__ out) {
    __shared__ __align__(16) float s_sh[8][XPAD];   // [row][k]
    __shared__ __align__(16) float u_sh[DD][8];
    __shared__ __align__(16) float r_sh[DD][8];
    __shared__ float am_sh[2][8];                   // att, mask for this step

    const int tid = threadIdx.x;
    const int blk = blockIdx.x;
    const int b0 = blk * 8;
    const int g = tid >> 7;
    const int d = tid & 127;

    const float* W = (g == 0) ? Wbu : ((g == 1) ? Wbr : Wbc);
    unsigned long long wp[DD / 2];
#pragma unroll
    for (int i = 0; i < DD / 2; i++)
        wp[i] = pk2(W[(2 * i) * DD + d], W[(2 * i + 1) * DD + d]);

    // init s: state0 rows b0..b0+7 -> s_sh[row][k]
    {
        int i0 = tid, i1 = tid + 384, i2 = tid + 768;
        s_sh[i0 >> 7][i0 & 127] = state0[(size_t)b0 * DD + i0];
        s_sh[i1 >> 7][i1 & 127] = state0[(size_t)b0 * DD + i1];
        if (tid < 256) s_sh[i2 >> 7][i2 & 127] = state0[(size_t)b0 * DD + i2];
    }
    __syncthreads();

    for (int t = 0; t < TT; t++) {
        // prefetch this step's x-projection (coalesced float4 pair) + att/mask
        const float* axp = g_Ax + (((size_t)t * (BB / 8) + blk) * NN + tid) * 8;
        float4 axA = *(const float4*)(axp + 0);
        float4 axB = *(const float4*)(axp + 4);
        if (tid < 8) {
            am_sh[0][tid] = att[t * BB + b0 + tid];
            am_sh[1][tid] = mask[(b0 + tid) * TT + t];
        }

        float m[8];
#pragma unroll
        for (int r = 0; r < 8; r++)
            m[r] = dot_row(&s_sh[r][0], wp);

        float ax[8] = {axA.x, axA.y, axA.z, axA.w, axB.x, axB.y, axB.z, axB.w};

        if (g == 0) {
            float v[8];
#pragma unroll
            for (int j = 0; j < 8; j++) v[j] = fsig(ax[j] + m[j]);
            *(float4*)&u_sh[d][0] = make_float4(v[0], v[1], v[2], v[3]);
            *(float4*)&u_sh[d][4] = make_float4(v[4], v[5], v[6], v[7]);
        } else if (g == 1) {
            float v[8];
#pragma unroll
            for (int j = 0; j < 8; j++) v[j] = fsig(ax[j] + m[j]);
            *(float4*)&r_sh[d][0] = make_float4(v[0], v[1], v[2], v[3]);
            *(float4*)&r_sh[d][4] = make_float4(v[4], v[5], v[6], v[7]);
        }
        __syncthreads();   // u,r,att,mask visible; matvec reads of s_sh complete

        if (g == 2) {
            float4 rA = *(const float4*)&r_sh[d][0];
            float4 rB = *(const float4*)&r_sh[d][4];
            float4 uA = *(const float4*)&u_sh[d][0];
            float4 uB = *(const float4*)&u_sh[d][4];
            float rr[8] = {rA.x, rA.y, rA.z, rA.w, rB.x, rB.y, rB.z, rB.w};
            float uu[8] = {uA.x, uA.y, uA.z, uA.w, uB.x, uB.y, uB.z, uB.w};
#pragma unroll
            for (int j = 0; j < 8; j++) {
                float cval = ftanh(ax[j] + rr[j] * m[j]);
                float ustar = am_sh[0][j] * uu[j];
                float so = s_sh[j][d];
                // s_new = m*((1-u)*s + u*c) + (1-m)*s == s + m*u*(c-s)
                s_sh[j][d] = so + am_sh[1][j] * (ustar * (cval - so));
            }
        }
        __syncthreads();   // s_sh update visible before next matvec
    }

    // write final state (coalesced within each row)
    {
        int i0 = tid, i1 = tid + 384, i2 = tid + 768;
        out[(size_t)b0 * DD + i0] = s_sh[i0 >> 7][i0 & 127];
        out[(size_t)b0 * DD + i1] = s_sh[i1 >> 7][i1 & 127];
        if (tid < 256) out[(size_t)b0 * DD + i2] = s_sh[i2 >> 7][i2 & 127];
    }
}

// ---------------- launch ----------------
extern "C" void kernel_launch(void* const* d_in, const int* in_sizes, int n_in,
                              void* d_out, int out_size) {
    const float* inputs = (const float*)d_in[0];   // [T,B,D]
    const float* state  = (const float*)d_in[1];   // [B,D]
    const float* att    = (const float*)d_in[2];   // [T,B,1]
    const float* mask   = (const float*)d_in[3];   // [B,T]
    // d_in[4] = max_len (compile-time TT)
    const float* Wau = (const float*)d_in[5];
    const float* bau = (const float*)d_in[6];
    const float* Wbu = (const float*)d_in[7];
    const float* War = (const float*)d_in[8];
    const float* bar = (const float*)d_in[9];
    const float* Wbr = (const float*)d_in[10];
    const float* Wac = (const float*)d_in[11];
    const float* bac = (const float*)d_in[12];
    const float* Wbc = (const float*)d_in[13];

    xproj_kernel<<<148, 384>>>(inputs, Wau, bau, War, bar, Wac, bac);
    recur_kernel<<<BB / 8, 384>>>(state, att, mask, Wbu, Wbr, Wbc, (float*)d_out);
}

// round 4
// speedup vs baseline: 1.4411x; 1.4411x over previous
#include <cuda_runtime.h>

#define TT 200
#define BB 1024
#define DD 128
#define NN 384      // 3 gates * 128
#define NPAIR 192   // column pairs
#define KH 64       // k-range per thread (k-half)
#define SROW 12     // padded row length (floats) for [k][row] tiles; 48B = 16B-aligned
#define RPAD 392    // red_sh row pad (floats)

// ---------------- device scratch (no runtime allocation allowed) ----------------
// g_Ax layout: [chunk][j][n], chunk = t*(BB/8)+blk, j = row within 8-row chunk.
__device__ float g_Ax[(size_t)TT * BB * NN];

// ---------------- f32x2 packed helpers ----------------
static __device__ __forceinline__ unsigned long long pk2(float lo, float hi) {
    unsigned long long r;
    asm("mov.b64 %0, {%1,%2};" : "=l"(r) : "f"(lo), "f"(hi));
    return r;
}
static __device__ __forceinline__ void upk2(unsigned long long v, float &lo, float &hi) {
    asm("mov.b64 {%0,%1}, %2;" : "=f"(lo), "=f"(hi) : "l"(v));
}
static __device__ __forceinline__ unsigned long long ffma2(unsigned long long a,
                                                           unsigned long long b,
                                                           unsigned long long c) {
    unsigned long long d;
    asm("fma.rn.f32x2 %0, %1, %2, %3;" : "=l"(d) : "l"(a), "l"(b), "l"(c));
    return d;
}

static __device__ __forceinline__ float fsig(float x) {
    return __fdividef(1.f, 1.f + __expf(-x));
}
static __device__ __forceinline__ float ftanh(float x) {
    float y = fminf(fmaxf(2.f * x, -30.f), 30.f);
    float e = __expf(y);
    return __fdividef(e - 1.f, e + 1.f);
}

// ---------------- cp.async ----------------
static __device__ __forceinline__ void cp16(void* dst_sh, const void* src) {
    unsigned s = (unsigned)__cvta_generic_to_shared(dst_sh);
    asm volatile("cp.async.cg.shared.global [%0], [%1], 16;" :: "r"(s), "l"(src));
}
static __device__ __forceinline__ void cp_commit() {
    asm volatile("cp.async.commit_group;");
}
static __device__ __forceinline__ void cp_wait0() {
    asm volatile("cp.async.wait_group 0;");
}

// One matvec pass over 4 rows: tile[k][row] (SROW-padded), ro = row offset (0 or 4).
// out0/out1 = partial sums for columns n0/n1, rows ro..ro+3, k in [k0, k0+KH).
static __device__ __forceinline__ void mv_pass(const float* __restrict__ tile, int ro, int k0,
                                               const float* __restrict__ w0,
                                               const float* __restrict__ w1,
                                               float out0[4], float out1[4]) {
    unsigned long long a00 = 0ull, a01 = 0ull, a10 = 0ull, a11 = 0ull;
    const float* base = tile + (size_t)k0 * SROW + ro;
#pragma unroll
    for (int i = 0; i < KH; i++) {
        ulonglong2 sv = *(const ulonglong2*)(base + (size_t)i * SROW);
        unsigned long long wp0 = pk2(w0[i], w0[i]);
        unsigned long long wp1 = pk2(w1[i], w1[i]);
        a00 = ffma2(sv.x, wp0, a00);
        a01 = ffma2(sv.y, wp0, a01);
        a10 = ffma2(sv.x, wp1, a10);
        a11 = ffma2(sv.y, wp1, a11);
    }
    upk2(a00, out0[0], out0[1]);
    upk2(a01, out0[2], out0[3]);
    upk2(a10, out1[0], out1[1]);
    upk2(a11, out1[2], out1[3]);
}

// ==================== phase 1: Ax = X @ [Wau|War|Wac] + bias ====================
__global__ __launch_bounds__(384, 1)
void xproj_kernel(const float* __restrict__ X,
                  const float* __restrict__ Wau, const float* __restrict__ bau,
                  const float* __restrict__ War, const float* __restrict__ bar,
                  const float* __restrict__ Wac, const float* __restrict__ bac) {
    __shared__ __align__(16) float x_sh[2][DD * SROW];   // [buf][k][row]
    __shared__ float red[2 * 8 * RPAD];                  // [h][j][n]
    __shared__ float b_sh[NN];

    const int tid = threadIdx.x;
    const int h = tid / NPAIR;          // k-half
    const int p = tid - h * NPAIR;      // column pair
    const int n0 = 2 * p, n1 = n0 + 1;
    const int k0 = h * KH;

    const float* W = (p < 64) ? Wau : ((p < 128) ? War : Wac);
    const int d0 = (p & 63) * 2;

    float w0[KH], w1[KH];
#pragma unroll
    for (int i = 0; i < KH; i++) {
        w0[i] = W[(k0 + i) * DD + d0];
        w1[i] = W[(k0 + i) * DD + d0 + 1];
    }
    {   // bias for column n = tid
        int g = tid >> 7, d = tid & 127;
        const float* bp = (g == 0) ? bau : ((g == 1) ? bar : bac);
        b_sh[tid] = bp[d];
    }

    const int NCHUNK = TT * BB / 8;   // 25600

    // stage chunk 0 into buf 0 (transpose [row][k] -> [k][row])
    int c = blockIdx.x;
    {
        const float* src = X + (size_t)c * (8 * DD);
        float v0 = src[tid];
        float v1 = src[tid + 384];
        float v2 = (tid < 256) ? src[tid + 768] : 0.f;
        int i0 = tid, i1 = tid + 384;
        x_sh[0][(i0 & 127) * SROW + (i0 >> 7)] = v0;
        x_sh[0][(i1 & 127) * SROW + (i1 >> 7)] = v1;
        if (tid < 256) { int i2 = tid + 768; x_sh[0][(i2 & 127) * SROW + (i2 >> 7)] = v2; }
    }
    __syncthreads();

    int buf = 0;
    for (; c < NCHUNK; c += gridDim.x) {
        const int cn = c + gridDim.x;
        float v0 = 0.f, v1 = 0.f, v2 = 0.f;
        if (cn < NCHUNK) {
            const float* src = X + (size_t)cn * (8 * DD);
            v0 = src[tid];
            v1 = src[tid + 384];
            v2 = (tid < 256) ? src[tid + 768] : 0.f;
        }

        // matvec: 2 passes of 4 rows each
        float o0[4], o1[4];
        mv_pass(x_sh[buf], 0, k0, w0, w1, o0, o1);
#pragma unroll
        for (int j = 0; j < 4; j++) {
            red[(h * 8 + j) * RPAD + n0] = o0[j];
            red[(h * 8 + j) * RPAD + n1] = o1[j];
        }
        mv_pass(x_sh[buf], 4, k0, w0, w1, o0, o1);
#pragma unroll
        for (int j = 0; j < 4; j++) {
            red[(h * 8 + j + 4) * RPAD + n0] = o0[j];
            red[(h * 8 + j + 4) * RPAD + n1] = o1[j];
        }

        // stage next chunk (other buffer; its readers finished at prior barrier)
        if (cn < NCHUNK) {
            int i0 = tid, i1 = tid + 384;
            x_sh[buf ^ 1][(i0 & 127) * SROW + (i0 >> 7)] = v0;
            x_sh[buf ^ 1][(i1 & 127) * SROW + (i1 >> 7)] = v1;
            if (tid < 256) { int i2 = tid + 768; x_sh[buf ^ 1][(i2 & 127) * SROW + (i2 >> 7)] = v2; }
        }
        __syncthreads();   // partials + staged tile visible

        // reduce k-halves + bias, write out: thread t owns column n = t, rows 0..7
        float* outp = g_Ax + (size_t)c * (8 * NN) + tid;
        float bias = b_sh[tid];
#pragma unroll
        for (int j = 0; j < 8; j++) {
            float m = red[j * RPAD + tid] + red[(8 + j) * RPAD + tid] + bias;
            outp[(size_t)j * NN] = m;
        }
        __syncthreads();   // red consumed; next iteration may overwrite
        buf ^= 1;
    }
}

// ==================== phase 2: recurrence, 1 CTA = 8 batch rows ====================
// dynamic smem layout (floats):
//   s_sh  [DD*SROW]        = 1536
//   red   [2*8*RPAD]       = 6272
//   act   [8*264]          = 2112   (u: n<128, r: 128<=n<256)
//   ax_sh [3072]                        ([j][n], mirrors g_Ax chunk)
//   am    [16]                          (att[8], mask[8])
#define RC_SMEM_FLOATS (DD * SROW + 2 * 8 * RPAD + 8 * 264 + 3072 + 16)

__global__ __launch_bounds__(384, 1)
void recur_kernel(const float* __restrict__ state0,
                  const float* __restrict__ att,    // [T,B,1]
                  const float* __restrict__ mask,   // [B,T]
                  const float* __restrict__ Wbu, const float* __restrict__ Wbr,
                  const float* __restrict__ Wbc,
                  float* __restrict__ out) {
    extern __shared__ __align__(16) float sm[];
    float* s_sh  = sm;                       // [k][row] (SROW pad)
    float* red   = s_sh + DD * SROW;         // [h][j][n]
    float* act   = red + 2 * 8 * RPAD;       // [j][n] n<256 (264 pad)
    float* ax_sh = act + 8 * 264;            // [j][n]
    float* am    = ax_sh + 3072;             // att[0..7], mask[8..15]

    const int tid = threadIdx.x;
    const int blk = blockIdx.x;
    const int b0 = blk * 8;
    const int h = tid / NPAIR;
    const int p = tid - h * NPAIR;
    const int n0 = 2 * p, n1 = n0 + 1;
    const int k0 = h * KH;

    const float* W = (p < 64) ? Wbu : ((p < 128) ? Wbr : Wbc);
    const int d0 = (p & 63) * 2;

    float w0[KH], w1[KH];
#pragma unroll
    for (int i = 0; i < KH; i++) {
        w0[i] = W[(k0 + i) * DD + d0];
        w1[i] = W[(k0 + i) * DD + d0 + 1];
    }

    // init s_sh[k][row] from state0[b0+j][k]
    {
        int i0 = tid, i1 = tid + 384, i2 = tid + 768;
        s_sh[(i0 & 127) * SROW + (i0 >> 7)] = state0[(size_t)b0 * DD + i0];
        s_sh[(i1 & 127) * SROW + (i1 >> 7)] = state0[(size_t)b0 * DD + i1];
        if (tid < 256) s_sh[(i2 & 127) * SROW + (i2 >> 7)] = state0[(size_t)b0 * DD + i2];
    }
    __syncthreads();

    for (int t = 0; t < TT; t++) {
        // async-stage this step's x-projection chunk [j][n] (12KB) + att/mask
        {
            const float* axg = g_Ax + ((size_t)t * (BB / 8) + blk) * (8 * NN);
            cp16(ax_sh + tid * 8, axg + tid * 8);
            cp16(ax_sh + tid * 8 + 4, axg + tid * 8 + 4);
            cp_commit();
            if (tid < 8) {
                am[tid] = att[t * BB + b0 + tid];
                am[8 + tid] = mask[(b0 + tid) * TT + t];
            }
        }

        // matvec partials: 2 passes of 4 rows
        float o0[4], o1[4];
        mv_pass(s_sh, 0, k0, w0, w1, o0, o1);
#pragma unroll
        for (int j = 0; j < 4; j++) {
            red[(h * 8 + j) * RPAD + n0] = o0[j];
            red[(h * 8 + j) * RPAD + n1] = o1[j];
        }
        mv_pass(s_sh, 4, k0, w0, w1, o0, o1);
#pragma unroll
        for (int j = 0; j < 4; j++) {
            red[(h * 8 + j + 4) * RPAD + n0] = o0[j];
            red[(h * 8 + j + 4) * RPAD + n1] = o1[j];
        }

        cp_wait0();
        __syncthreads();   // B1: partials + ax + am visible; s_sh reads done

        // activations: thread t<256 owns column n=t (u for n<128, r for 128..255)
        if (tid < 256) {
#pragma unroll
            for (int j = 0; j < 8; j++) {
                float m = red[j * RPAD + tid] + red[(8 + j) * RPAD + tid];
                act[j * 264 + tid] = fsig(ax_sh[j * NN + tid] + m);
            }
        }
        __syncthreads();   // B2: u,r visible

        // candidate + state update: thread t<128 owns c-column n=256+t, feature d=t
        if (tid < 128) {
            const int n = 256 + tid;
#pragma unroll
            for (int j = 0; j < 8; j++) {
                float m = red[j * RPAD + n] + red[(8 + j) * RPAD + n];
                float cval = ftanh(ax_sh[j * NN + n] + act[j * 264 + 128 + tid] * m);
                float ustar = am[j] * act[j * 264 + tid];
                float so = s_sh[tid * SROW + j];
                // s_new = m*((1-u)*s + u*c) + (1-m)*s == s + m*u*(c-s)
                s_sh[tid * SROW + j] = so + am[8 + j] * (ustar * (cval - so));
            }
        }
        __syncthreads();   // B3: s ready for next matvec; ax_sh/red reusable
    }

    // write final state
    {
        int i0 = tid, i1 = tid + 384, i2 = tid + 768;
        out[(size_t)b0 * DD + i0] = s_sh[(i0 & 127) * SROW + (i0 >> 7)];
        out[(size_t)b0 * DD + i1] = s_sh[(i1 & 127) * SROW + (i1 >> 7)];
        if (tid < 256) out[(size_t)b0 * DD + i2] = s_sh[(i2 & 127) * SROW + (i2 >> 7)];
    }
}

// ---------------- launch ----------------
extern "C" void kernel_launch(void* const* d_in, const int* in_sizes, int n_in,
                              void* d_out, int out_size) {
    const float* inputs = (const float*)d_in[0];   // [T,B,D]
    const float* state  = (const float*)d_in[1];   // [B,D]
    const float* att    = (const float*)d_in[2];   // [T,B,1]
    const float* mask   = (const float*)d_in[3];   // [B,T]
    // d_in[4] = max_len (compile-time TT)
    const float* Wau = (const float*)d_in[5];
    const float* bau = (const float*)d_in[6];
    const float* Wbu = (const float*)d_in[7];
    const float* War = (const float*)d_in[8];
    const float* bar = (const float*)d_in[9];
    const float* Wbr = (const float*)d_in[10];
    const float* Wac = (const float*)d_in[11];
    const float* bac = (const float*)d_in[12];
    const float* Wbc = (const float*)d_in[13];

    const int rc_smem = RC_SMEM_FLOATS * (int)sizeof(float);
    cudaFuncSetAttribute(recur_kernel, cudaFuncAttributeMaxDynamicSharedMemorySize, rc_smem);

    xproj_kernel<<<148, 384>>>(inputs, Wau, bau, War, bar, Wac, bac);
    recur_kernel<<<BB / 8, 384, rc_smem>>>(state, att, mask, Wbu, Wbr, Wbc, (float*)d_out);
}

// round 6
// speedup vs baseline: 1.9196x; 1.3321x over previous
#include <cuda_runtime.h>
#include <cuda_bf16.h>

#define TT 200
#define BB 1024
#define DD 128
#define NN 384        // 3 gates * 128
#define NCH 1600      // (TT*BB)/128 row-chunks
#define GCH 48        // chunk stride per gemm CTA (144 CTAs = 3 gates * 48)
#define XP 136        // padded k-length (bf16 elems) for smem tiles -> conflict-free frags
// recur params
#define SROW 12
#define RPAD 392
#define NPAIR 192
#define KH 64

// ---------------- device scratch (no runtime allocation allowed) ----------------
__device__ float g_Ax[(size_t)TT * BB * NN];                       // [row][n] row-major
__device__ __align__(16) __nv_bfloat16 g_Xhi[(size_t)TT * BB * DD];
__device__ __align__(16) __nv_bfloat16 g_Xlo[(size_t)TT * BB * DD];
__device__ __align__(16) __nv_bfloat16 g_Whi[3 * DD * DD];         // [gate][n][k]
__device__ __align__(16) __nv_bfloat16 g_Wlo[3 * DD * DD];

// ---------------- PTX helpers ----------------
static __device__ __forceinline__ void cp16(void* dst_sh, const void* src) {
    unsigned s = (unsigned)__cvta_generic_to_shared(dst_sh);
    asm volatile("cp.async.cg.shared.global [%0], [%1], 16;" :: "r"(s), "l"(src));
}
static __device__ __forceinline__ void cp_commit() { asm volatile("cp.async.commit_group;"); }
static __device__ __forceinline__ void cp_wait0() { asm volatile("cp.async.wait_group 0;"); }
static __device__ __forceinline__ void cp_wait1() { asm volatile("cp.async.wait_group 1;"); }

// bf16 mma, fp32 accumulate, baseline PTX (works at compute_103)
static __device__ __forceinline__ void mma16816(float* d, const unsigned* a, const unsigned* b) {
    asm volatile(
        "mma.sync.aligned.m16n8k16.row.col.f32.bf16.bf16.f32 "
        "{%0,%1,%2,%3}, {%4,%5,%6,%7}, {%8,%9}, {%0,%1,%2,%3};"
        : "+f"(d[0]), "+f"(d[1]), "+f"(d[2]), "+f"(d[3])
        : "r"(a[0]), "r"(a[1]), "r"(a[2]), "r"(a[3]), "r"(b[0]), "r"(b[1]));
}

// ---------------- f32x2 packed helpers (recur) ----------------
static __device__ __forceinline__ unsigned long long pk2(float lo, float hi) {
    unsigned long long r;
    asm("mov.b64 %0, {%1,%2};" : "=l"(r) : "f"(lo), "f"(hi));
    return r;
}
static __device__ __forceinline__ void upk2(unsigned long long v, float &lo, float &hi) {
    asm("mov.b64 {%0,%1}, %2;" : "=f"(lo), "=f"(hi) : "l"(v));
}
static __device__ __forceinline__ unsigned long long ffma2(unsigned long long a,
                                                           unsigned long long b,
                                                           unsigned long long c) {
    unsigned long long d;
    asm("fma.rn.f32x2 %0, %1, %2, %3;" : "=l"(d) : "l"(a), "l"(b), "l"(c));
    return d;
}
static __device__ __forceinline__ float fsig(float x) {
    return __fdividef(1.f, 1.f + __expf(-x));
}
static __device__ __forceinline__ float ftanh(float x) {
    float y = fminf(fmaxf(2.f * x, -30.f), 30.f);
    float e = __expf(y);
    return __fdividef(e - 1.f, e + 1.f);
}
static __device__ __forceinline__ unsigned pack2bf(__nv_bfloat16 a, __nv_bfloat16 b) {
    return (unsigned)__bfloat16_as_ushort(a) | ((unsigned)__bfloat16_as_ushort(b) << 16);
}

// ==================== prep: X -> bf16 hi/lo (row-major, same layout as X) ====================
__global__ void prep_x(const float4* __restrict__ X4) {
    const size_t n4 = (size_t)TT * BB * DD / 4;
    for (size_t i = (size_t)blockIdx.x * blockDim.x + threadIdx.x; i < n4;
         i += (size_t)gridDim.x * blockDim.x) {
        float4 v = X4[i];
        __nv_bfloat16 hx = __float2bfloat16(v.x), hy = __float2bfloat16(v.y);
        __nv_bfloat16 hz = __float2bfloat16(v.z), hw = __float2bfloat16(v.w);
        uint2 h, l;
        h.x = pack2bf(hx, hy);
        h.y = pack2bf(hz, hw);
        l.x = pack2bf(__float2bfloat16(v.x - __bfloat162float(hx)),
                      __float2bfloat16(v.y - __bfloat162float(hy)));
        l.y = pack2bf(__float2bfloat16(v.z - __bfloat162float(hz)),
                      __float2bfloat16(v.w - __bfloat162float(hw)));
        ((uint2*)g_Xhi)[i] = h;
        ((uint2*)g_Xlo)[i] = l;
    }
}

// ==================== prep: W -> transposed [n][k] bf16 hi/lo ====================
__global__ void prep_w(const float* __restrict__ Wau, const float* __restrict__ War,
                       const float* __restrict__ Wac) {
    const int g = blockIdx.x;
    const float* W = (g == 0) ? Wau : ((g == 1) ? War : Wac);
    for (int idx = threadIdx.x; idx < DD * DD; idx += blockDim.x) {
        int n = idx >> 7, k = idx & 127;
        float v = W[k * DD + n];
        __nv_bfloat16 hi = __float2bfloat16(v);
        g_Whi[g * DD * DD + idx] = hi;
        g_Wlo[g * DD * DD + idx] = __float2bfloat16(v - __bfloat162float(hi));
    }
}

// ==================== phase 1 GEMM (mma.sync bf16, split-3): g_Ax = X @ Wg ====================
// smem: Xbuf[2 bufs][2 splits][128][XP] + Wp[2 splits][128][XP], bf16
#define XTC_SMEM (6 * DD * XP * 2)   // 208896 bytes

static __device__ __forceinline__ void stageX(__nv_bfloat16* dst, int c, int tid) {
#pragma unroll
    for (int q = 0; q < 16; q++) {
        int id = q * 256 + tid;           // 0..4095
        int sp = id >> 11;                // split
        int rr = (id >> 4) & 127;         // row
        int sg = id & 15;                 // 16B segment
        const __nv_bfloat16* src = (sp ? g_Xlo : g_Xhi) + (size_t)c * (DD * DD) + rr * DD + sg * 8;
        cp16(dst + sp * (DD * XP) + rr * XP + sg * 8, src);
    }
}

__global__ __launch_bounds__(256, 1) void xproj_tc() {
    extern __shared__ __align__(16) __nv_bfloat16 smp[];
    __nv_bfloat16* Xb0 = smp;
    __nv_bfloat16* Xb1 = smp + 2 * DD * XP;
    __nv_bfloat16* Wp  = smp + 4 * DD * XP;

    const int tid = threadIdx.x;
    const int gate = blockIdx.x / GCH;
    const int part = blockIdx.x % GCH;
    const int wid = tid >> 5, lane = tid & 31;
    const int g = lane >> 2, tg = lane & 3;
    const int wm = wid >> 2, wn = wid & 3;      // warp grid 2(M) x 4(N)

    // group 0: W (both splits) + first X chunk
#pragma unroll
    for (int q = 0; q < 16; q++) {
        int id = q * 256 + tid;
        int sp = id >> 11, rr = (id >> 4) & 127, sg = id & 15;
        const __nv_bfloat16* src = (sp ? g_Wlo : g_Whi) + gate * DD * DD + rr * DD + sg * 8;
        cp16(Wp + sp * (DD * XP) + rr * XP + sg * 8, src);
    }
    stageX(Xb0, part, tid);
    cp_commit();

    int buf = 0;
    for (int c = part; c < NCH; c += GCH) {
        const int cn = c + GCH;
        if (cn < NCH) stageX(buf ? Xb0 : Xb1, cn, tid);
        cp_commit();
        cp_wait1();          // current chunk (and W on iter 0) ready
        __syncthreads();

        const __nv_bfloat16* Xhi_s = buf ? Xb1 : Xb0;
        const __nv_bfloat16* Xlo_s = Xhi_s + DD * XP;
        const __nv_bfloat16* Whi_s = Wp;
        const __nv_bfloat16* Wlo_s = Wp + DD * XP;

        float acc[4][4][4];
#pragma unroll
        for (int mt = 0; mt < 4; mt++)
#pragma unroll
            for (int nt = 0; nt < 4; nt++)
#pragma unroll
                for (int q = 0; q < 4; q++) acc[mt][nt][q] = 0.f;

        const int arow = wm * 64 + g;
        const int bcol = wn * 32 + g;

#pragma unroll
        for (int ks = 0; ks < 8; ks++) {
            const int k0 = ks * 16 + 2 * tg;
            unsigned ah[4][4], bh[4][2];
#pragma unroll
            for (int mt = 0; mt < 4; mt++) {
                const __nv_bfloat16* pa = Xhi_s + (arow + mt * 16) * XP + k0;
                ah[mt][0] = *(const unsigned*)pa;
                ah[mt][1] = *(const unsigned*)(pa + 8 * XP);
                ah[mt][2] = *(const unsigned*)(pa + 8);
                ah[mt][3] = *(const unsigned*)(pa + 8 * XP + 8);
            }
#pragma unroll
            for (int nt = 0; nt < 4; nt++) {
                const __nv_bfloat16* pb = Whi_s + (bcol + nt * 8) * XP + k0;
                bh[nt][0] = *(const unsigned*)pb;
                bh[nt][1] = *(const unsigned*)(pb + 8);
            }
            // product 1: A_hi * W_hi
#pragma unroll
            for (int mt = 0; mt < 4; mt++)
#pragma unroll
                for (int nt = 0; nt < 4; nt++) mma16816(acc[mt][nt], ah[mt], bh[nt]);
            // product 2: A_lo * W_hi
            {
                unsigned al[4][4];
#pragma unroll
                for (int mt = 0; mt < 4; mt++) {
                    const __nv_bfloat16* pa = Xlo_s + (arow + mt * 16) * XP + k0;
                    al[mt][0] = *(const unsigned*)pa;
                    al[mt][1] = *(const unsigned*)(pa + 8 * XP);
                    al[mt][2] = *(const unsigned*)(pa + 8);
                    al[mt][3] = *(const unsigned*)(pa + 8 * XP + 8);
                }
#pragma unroll
                for (int mt = 0; mt < 4; mt++)
#pragma unroll
                    for (int nt = 0; nt < 4; nt++) mma16816(acc[mt][nt], al[mt], bh[nt]);
            }
            // product 3: A_hi * W_lo
            {
                unsigned bl[4][2];
#pragma unroll
                for (int nt = 0; nt < 4; nt++) {
                    const __nv_bfloat16* pb = Wlo_s + (bcol + nt * 8) * XP + k0;
                    bl[nt][0] = *(const unsigned*)pb;
                    bl[nt][1] = *(const unsigned*)(pb + 8);
                }
#pragma unroll
                for (int mt = 0; mt < 4; mt++)
#pragma unroll
                    for (int nt = 0; nt < 4; nt++) mma16816(acc[mt][nt], ah[mt], bl[nt]);
            }
        }

        // epilogue: D[m][n] -> g_Ax[row][gate*128 + n]
        const size_t rbase = (size_t)c * 128;
#pragma unroll
        for (int mt = 0; mt < 4; mt++) {
#pragma unroll
            for (int nt = 0; nt < 4; nt++) {
                size_t r1 = rbase + wm * 64 + mt * 16 + g;
                int col = gate * 128 + wn * 32 + nt * 8 + 2 * tg;
                *(float2*)&g_Ax[r1 * NN + col] =
                    make_float2(acc[mt][nt][0], acc[mt][nt][1]);
                *(float2*)&g_Ax[(r1 + 8) * NN + col] =
                    make_float2(acc[mt][nt][2], acc[mt][nt][3]);
            }
        }
        __syncthreads();   // all reads of both buffers done before next prefetch
        buf ^= 1;
    }
}

// ==================== phase 2: recurrence (proven 642us version, bias added) ====================
#define RC_SMEM_FLOATS (DD * SROW + 2 * 8 * RPAD + 8 * 264 + 3072 + 16 + NN)

static __device__ __forceinline__ void mv_pass(const float* __restrict__ tile, int ro, int k0,
                                               const float* __restrict__ w0,
                                               const float* __restrict__ w1,
                                               float out0[4], float out1[4]) {
    unsigned long long a00 = 0ull, a01 = 0ull, a10 = 0ull, a11 = 0ull;
    const float* base = tile + (size_t)k0 * SROW + ro;
#pragma unroll
    for (int i = 0; i < KH; i++) {
        ulonglong2 sv = *(const ulonglong2*)(base + (size_t)i * SROW);
        unsigned long long wp0 = pk2(w0[i], w0[i]);
        unsigned long long wp1 = pk2(w1[i], w1[i]);
        a00 = ffma2(sv.x, wp0, a00);
        a01 = ffma2(sv.y, wp0, a01);
        a10 = ffma2(sv.x, wp1, a10);
        a11 = ffma2(sv.y, wp1, a11);
    }
    upk2(a00, out0[0], out0[1]);
    upk2(a01, out0[2], out0[3]);
    upk2(a10, out1[0], out1[1]);
    upk2(a11, out1[2], out1[3]);
}

__global__ __launch_bounds__(384, 1)
void recur_kernel(const float* __restrict__ state0,
                  const float* __restrict__ att,    // [T,B,1]
                  const float* __restrict__ mask,   // [B,T]
                  const float* __restrict__ bau, const float* __restrict__ bar,
                  const float* __restrict__ bac,
                  const float* __restrict__ Wbu, const float* __restrict__ Wbr,
                  const float* __restrict__ Wbc,
                  float* __restrict__ out) {
    extern __shared__ __align__(16) float sm[];
    float* s_sh  = sm;                       // [k][row] (SROW pad)
    float* red   = s_sh + DD * SROW;         // [h][j][n]
    float* act   = red + 2 * 8 * RPAD;       // [j][n] n<256 (264 pad)
    float* ax_sh = act + 8 * 264;            // [j][n]
    float* am    = ax_sh + 3072;             // att[0..7], mask[8..15]
    float* b_sh  = am + 16;                  // bias [384]

    const int tid = threadIdx.x;
    const int blk = blockIdx.x;
    const int b0 = blk * 8;
    const int h = tid / NPAIR;
    const int p = tid - h * NPAIR;
    const int n0 = 2 * p, n1 = n0 + 1;
    const int k0 = h * KH;

    const float* W = (p < 64) ? Wbu : ((p < 128) ? Wbr : Wbc);
    const int d0 = (p & 63) * 2;

    float w0[KH], w1[KH];
#pragma unroll
    for (int i = 0; i < KH; i++) {
        w0[i] = W[(k0 + i) * DD + d0];
        w1[i] = W[(k0 + i) * DD + d0 + 1];
    }

    {   // bias for column n = tid
        int g = tid >> 7, d = tid & 127;
        const float* bp = (g == 0) ? bau : ((g == 1) ? bar : bac);
        b_sh[tid] = bp[d];
    }

    // init s_sh[k][row] from state0[b0+j][k]
    {
        int i0 = tid, i1 = tid + 384, i2 = tid + 768;
        s_sh[(i0 & 127) * SROW + (i0 >> 7)] = state0[(size_t)b0 * DD + i0];
        s_sh[(i1 & 127) * SROW + (i1 >> 7)] = state0[(size_t)b0 * DD + i1];
        if (tid < 256) s_sh[(i2 & 127) * SROW + (i2 >> 7)] = state0[(size_t)b0 * DD + i2];
    }
    __syncthreads();

    for (int t = 0; t < TT; t++) {
        // async-stage this step's x-projection chunk [j][n] (12KB) + att/mask
        {
            const float* axg = g_Ax + ((size_t)t * (BB / 8) + blk) * (8 * NN);
            cp16(ax_sh + tid * 8, axg + tid * 8);
            cp16(ax_sh + tid * 8 + 4, axg + tid * 8 + 4);
            cp_commit();
            if (tid < 8) {
                am[tid] = att[t * BB + b0 + tid];
                am[8 + tid] = mask[(b0 + tid) * TT + t];
            }
        }

        // matvec partials: 2 passes of 4 rows
        float o0[4], o1[4];
        mv_pass(s_sh, 0, k0, w0, w1, o0, o1);
#pragma unroll
        for (int j = 0; j < 4; j++) {
            red[(h * 8 + j) * RPAD + n0] = o0[j];
            red[(h * 8 + j) * RPAD + n1] = o1[j];
        }
        mv_pass(s_sh, 4, k0, w0, w1, o0, o1);
#pragma unroll
        for (int j = 0; j < 4; j++) {
            red[(h * 8 + j + 4) * RPAD + n0] = o0[j];
            red[(h * 8 + j + 4) * RPAD + n1] = o1[j];
        }

        cp_wait0();
        __syncthreads();   // B1: partials + ax + am visible; s_sh reads done

        // activations: thread t<256 owns column n=t (u for n<128, r for 128..255)
        if (tid < 256) {
            float bb = b_sh[tid];
#pragma unroll
            for (int j = 0; j < 8; j++) {
                float m = red[j * RPAD + tid] + red[(8 + j) * RPAD + tid];
                act[j * 264 + tid] = fsig(ax_sh[j * NN + tid] + bb + m);
            }
        }
        __syncthreads();   // B2: u,r visible

        // candidate + state update: thread t<128 owns c-column n=256+t, feature d=t
        if (tid < 128) {
            const int n = 256 + tid;
            float bc = b_sh[n];
#pragma unroll
            for (int j = 0; j < 8; j++) {
                float m = red[j * RPAD + n] + red[(8 + j) * RPAD + n];
                float cval = ftanh(ax_sh[j * NN + n] + bc + act[j * 264 + 128 + tid] * m);
                float ustar = am[j] * act[j * 264 + tid];
                float so = s_sh[tid * SROW + j];
                // s_new = m*((1-u)*s + u*c) + (1-m)*s == s + m*u*(c-s)
                s_sh[tid * SROW + j] = so + am[8 + j] * (ustar * (cval - so));
            }
        }
        __syncthreads();   // B3: s ready for next matvec
    }

    // write final state
    {
        int i0 = tid, i1 = tid + 384, i2 = tid + 768;
        out[(size_t)b0 * DD + i0] = s_sh[(i0 & 127) * SROW + (i0 >> 7)];
        out[(size_t)b0 * DD + i1] = s_sh[(i1 & 127) * SROW + (i1 >> 7)];
        if (tid < 256) out[(size_t)b0 * DD + i2] = s_sh[(i2 & 127) * SROW + (i2 >> 7)];
    }
}

// ---------------- launch ----------------
extern "C" void kernel_launch(void* const* d_in, const int* in_sizes, int n_in,
                              void* d_out, int out_size) {
    const float* inputs = (const float*)d_in[0];   // [T,B,D]
    const float* state  = (const float*)d_in[1];   // [B,D]
    const float* att    = (const float*)d_in[2];   // [T,B,1]
    const float* mask   = (const float*)d_in[3];   // [B,T]
    // d_in[4] = max_len (compile-time TT)
    const float* Wau = (const float*)d_in[5];
    const float* bau = (const float*)d_in[6];
    const float* Wbu = (const float*)d_in[7];
    const float* War = (const float*)d_in[8];
    const float* bar = (const float*)d_in[9];
    const float* Wbr = (const float*)d_in[10];
    const float* Wac = (const float*)d_in[11];
    const float* bac = (const float*)d_in[12];
    const float* Wbc = (const float*)d_in[13];

    const int rc_smem = RC_SMEM_FLOATS * (int)sizeof(float);
    cudaFuncSetAttribute(recur_kernel, cudaFuncAttributeMaxDynamicSharedMemorySize, rc_smem);
    cudaFuncSetAttribute(xproj_tc, cudaFuncAttributeMaxDynamicSharedMemorySize, XTC_SMEM);

    prep_w<<<3, 256>>>(Wau, War, Wac);
    prep_x<<<2048, 256>>>((const float4*)inputs);
    xproj_tc<<<3 * GCH, 256, XTC_SMEM>>>();
    recur_kernel<<<BB / 8, 384, rc_smem>>>(state, att, mask, bau, bar, bac,
                                           Wbu, Wbr, Wbc, (float*)d_out);
}

// round 7
// speedup vs baseline: 1.9435x; 1.0125x over previous
#include <cuda_runtime.h>
#include <cuda_bf16.h>

#define TT 200
#define BB 1024
#define DD 128
#define NN 384        // 3 gates * 128
#define NCH 1600      // (TT*BB)/128 row-chunks
#define GCH 48        // chunk stride per gemm CTA (144 CTAs = 3 gates * 48)
#define XP 136        // padded k-length (bf16) for xproj smem tiles

// ---------------- device scratch (no runtime allocation allowed) ----------------
__device__ float g_Ax[(size_t)TT * BB * NN];                       // [row][n] row-major
__device__ __align__(16) __nv_bfloat16 g_Xhi[(size_t)TT * BB * DD];
__device__ __align__(16) __nv_bfloat16 g_Xlo[(size_t)TT * BB * DD];
__device__ __align__(16) __nv_bfloat16 g_Whi[3 * DD * DD];         // [gate][n][k]
__device__ __align__(16) __nv_bfloat16 g_Wlo[3 * DD * DD];

// ---------------- PTX helpers ----------------
static __device__ __forceinline__ void cp16(void* dst_sh, const void* src) {
    unsigned s = (unsigned)__cvta_generic_to_shared(dst_sh);
    asm volatile("cp.async.cg.shared.global [%0], [%1], 16;" :: "r"(s), "l"(src));
}
static __device__ __forceinline__ void cp_commit() { asm volatile("cp.async.commit_group;"); }
static __device__ __forceinline__ void cp_wait1() { asm volatile("cp.async.wait_group 1;"); }

// bf16 mma, fp32 accumulate, baseline PTX (compiles at compute_103)
static __device__ __forceinline__ void mma16816(float* d, const unsigned* a, const unsigned* b) {
    asm volatile(
        "mma.sync.aligned.m16n8k16.row.col.f32.bf16.bf16.f32 "
        "{%0,%1,%2,%3}, {%4,%5,%6,%7}, {%8,%9}, {%0,%1,%2,%3};"
        : "+f"(d[0]), "+f"(d[1]), "+f"(d[2]), "+f"(d[3])
        : "r"(a[0]), "r"(a[1]), "r"(a[2]), "r"(a[3]), "r"(b[0]), "r"(b[1]));
}

static __device__ __forceinline__ float fsig(float x) {
    return __fdividef(1.f, 1.f + __expf(-x));
}
static __device__ __forceinline__ float ftanh(float x) {
    float y = fminf(fmaxf(2.f * x, -30.f), 30.f);
    float e = __expf(y);
    return __fdividef(e - 1.f, e + 1.f);
}
static __device__ __forceinline__ unsigned pack2bf(__nv_bfloat16 a, __nv_bfloat16 b) {
    return (unsigned)__bfloat16_as_ushort(a) | ((unsigned)__bfloat16_as_ushort(b) << 16);
}

// k -> interleaved word index within a 64-word (128 bf16) row.
// word [ks*8 + q*2 + 0] holds k = ks*16 + 2q, +1 ; word [.. + 1] holds k+8 pair.
// One LDS.64 at (ks*8 + q*2) returns (b0, b1) / (a0a1, a4a5) fragments directly.
static __device__ __forceinline__ int word_of(int k) {
    int ks = k >> 4, r16 = k & 15;
    return ks * 8 + (((r16 & 7) >> 1) << 1) + (r16 >> 3);
}

// ==================== prep: X -> bf16 hi/lo (row-major) ====================
__global__ void prep_x(const float4* __restrict__ X4) {
    const size_t n4 = (size_t)TT * BB * DD / 4;
    for (size_t i = (size_t)blockIdx.x * blockDim.x + threadIdx.x; i < n4;
         i += (size_t)gridDim.x * blockDim.x) {
        float4 v = X4[i];
        __nv_bfloat16 hx = __float2bfloat16(v.x), hy = __float2bfloat16(v.y);
        __nv_bfloat16 hz = __float2bfloat16(v.z), hw = __float2bfloat16(v.w);
        uint2 h, l;
        h.x = pack2bf(hx, hy);
        h.y = pack2bf(hz, hw);
        l.x = pack2bf(__float2bfloat16(v.x - __bfloat162float(hx)),
                      __float2bfloat16(v.y - __bfloat162float(hy)));
        l.y = pack2bf(__float2bfloat16(v.z - __bfloat162float(hz)),
                      __float2bfloat16(v.w - __bfloat162float(hw)));
        ((uint2*)g_Xhi)[i] = h;
        ((uint2*)g_Xlo)[i] = l;
    }
}

// ==================== prep: Wa -> transposed [n][k] bf16 hi/lo ====================
__global__ void prep_w(const float* __restrict__ Wau, const float* __restrict__ War,
                       const float* __restrict__ Wac) {
    const int g = blockIdx.x;
    const float* W = (g == 0) ? Wau : ((g == 1) ? War : Wac);
    for (int idx = threadIdx.x; idx < DD * DD; idx += blockDim.x) {
        int n = idx >> 7, k = idx & 127;
        float v = W[k * DD + n];
        __nv_bfloat16 hi = __float2bfloat16(v);
        g_Whi[g * DD * DD + idx] = hi;
        g_Wlo[g * DD * DD + idx] = __float2bfloat16(v - __bfloat162float(hi));
    }
}

// ==================== phase 1 GEMM (mma.sync bf16, split-3): g_Ax = X @ Wg ====================
#define XTC_SMEM (6 * DD * XP * 2)   // 208896 bytes

static __device__ __forceinline__ void stageX(__nv_bfloat16* dst, int c, int tid) {
#pragma unroll
    for (int q = 0; q < 16; q++) {
        int id = q * 256 + tid;
        int sp = id >> 11, rr = (id >> 4) & 127, sg = id & 15;
        const __nv_bfloat16* src = (sp ? g_Xlo : g_Xhi) + (size_t)c * (DD * DD) + rr * DD + sg * 8;
        cp16(dst + sp * (DD * XP) + rr * XP + sg * 8, src);
    }
}

__global__ __launch_bounds__(256, 1) void xproj_tc() {
    extern __shared__ __align__(16) __nv_bfloat16 smp[];
    __nv_bfloat16* Xb0 = smp;
    __nv_bfloat16* Xb1 = smp + 2 * DD * XP;
    __nv_bfloat16* Wp  = smp + 4 * DD * XP;

    const int tid = threadIdx.x;
    const int gate = blockIdx.x / GCH;
    const int part = blockIdx.x % GCH;
    const int wid = tid >> 5, lane = tid & 31;
    const int g = lane >> 2, tg = lane & 3;
    const int wm = wid >> 2, wn = wid & 3;

#pragma unroll
    for (int q = 0; q < 16; q++) {
        int id = q * 256 + tid;
        int sp = id >> 11, rr = (id >> 4) & 127, sg = id & 15;
        const __nv_bfloat16* src = (sp ? g_Wlo : g_Whi) + gate * DD * DD + rr * DD + sg * 8;
        cp16(Wp + sp * (DD * XP) + rr * XP + sg * 8, src);
    }
    stageX(Xb0, part, tid);
    cp_commit();

    int buf = 0;
    for (int c = part; c < NCH; c += GCH) {
        const int cn = c + GCH;
        if (cn < NCH) stageX(buf ? Xb0 : Xb1, cn, tid);
        cp_commit();
        cp_wait1();
        __syncthreads();

        const __nv_bfloat16* Xhi_s = buf ? Xb1 : Xb0;
        const __nv_bfloat16* Xlo_s = Xhi_s + DD * XP;
        const __nv_bfloat16* Whi_s = Wp;
        const __nv_bfloat16* Wlo_s = Wp + DD * XP;

        float acc[4][4][4];
#pragma unroll
        for (int mt = 0; mt < 4; mt++)
#pragma unroll
            for (int nt = 0; nt < 4; nt++)
#pragma unroll
                for (int q = 0; q < 4; q++) acc[mt][nt][q] = 0.f;

        const int arow = wm * 64 + g;
        const int bcol = wn * 32 + g;

#pragma unroll
        for (int ks = 0; ks < 8; ks++) {
            const int k0 = ks * 16 + 2 * tg;
            unsigned ah[4][4], bh[4][2];
#pragma unroll
            for (int mt = 0; mt < 4; mt++) {
                const __nv_bfloat16* pa = Xhi_s + (arow + mt * 16) * XP + k0;
                ah[mt][0] = *(const unsigned*)pa;
                ah[mt][1] = *(const unsigned*)(pa + 8 * XP);
                ah[mt][2] = *(const unsigned*)(pa + 8);
                ah[mt][3] = *(const unsigned*)(pa + 8 * XP + 8);
            }
#pragma unroll
            for (int nt = 0; nt < 4; nt++) {
                const __nv_bfloat16* pb = Whi_s + (bcol + nt * 8) * XP + k0;
                bh[nt][0] = *(const unsigned*)pb;
                bh[nt][1] = *(const unsigned*)(pb + 8);
            }
#pragma unroll
            for (int mt = 0; mt < 4; mt++)
#pragma unroll
                for (int nt = 0; nt < 4; nt++) mma16816(acc[mt][nt], ah[mt], bh[nt]);
            {
                unsigned al[4][4];
#pragma unroll
                for (int mt = 0; mt < 4; mt++) {
                    const __nv_bfloat16* pa = Xlo_s + (arow + mt * 16) * XP + k0;
                    al[mt][0] = *(const unsigned*)pa;
                    al[mt][1] = *(const unsigned*)(pa + 8 * XP);
                    al[mt][2] = *(const unsigned*)(pa + 8);
                    al[mt][3] = *(const unsigned*)(pa + 8 * XP + 8);
                }
#pragma unroll
                for (int mt = 0; mt < 4; mt++)
#pragma unroll
                    for (int nt = 0; nt < 4; nt++) mma16816(acc[mt][nt], al[mt], bh[nt]);
            }
            {
                unsigned bl[4][2];
#pragma unroll
                for (int nt = 0; nt < 4; nt++) {
                    const __nv_bfloat16* pb = Wlo_s + (bcol + nt * 8) * XP + k0;
                    bl[nt][0] = *(const unsigned*)pb;
                    bl[nt][1] = *(const unsigned*)(pb + 8);
                }
#pragma unroll
                for (int mt = 0; mt < 4; mt++)
#pragma unroll
                    for (int nt = 0; nt < 4; nt++) mma16816(acc[mt][nt], ah[mt], bl[nt]);
            }
        }

        const size_t rbase = (size_t)c * 128;
#pragma unroll
        for (int mt = 0; mt < 4; mt++) {
#pragma unroll
            for (int nt = 0; nt < 4; nt++) {
                size_t r1 = rbase + wm * 64 + mt * 16 + g;
                int col = gate * 128 + wn * 32 + nt * 8 + 2 * tg;
                *(float2*)&g_Ax[r1 * NN + col] = make_float2(acc[mt][nt][0], acc[mt][nt][1]);
                *(float2*)&g_Ax[(r1 + 8) * NN + col] = make_float2(acc[mt][nt][2], acc[mt][nt][3]);
            }
        }
        __syncthreads();
        buf ^= 1;
    }
}

// ==================== phase 2: recurrence on mma.sync (split-bf16) ====================
// 128 CTAs x 8 batch rows, 256 threads (8 warps).
// smem (bytes): Whi 98304 | Wlo 98304 | sA [2][16][64] words 8192 | sf 8*132*4 | pre 8*392*4
#define OFF_WLO 98304
#define OFF_SA  196608
#define OFF_SF  204800
#define OFF_PRE 209024
#define RC_SMEM 221568

__global__ __launch_bounds__(256, 1)
void recur_tc(const float* __restrict__ state0,
              const float* __restrict__ att,    // [T,B,1]
              const float* __restrict__ mask,   // [B,T]
              const float* __restrict__ bau, const float* __restrict__ bar,
              const float* __restrict__ bac,
              const float* __restrict__ Wbu, const float* __restrict__ Wbr,
              const float* __restrict__ Wbc,
              float* __restrict__ out) {
    extern __shared__ char sm[];
    unsigned* Whi = (unsigned*)sm;
    unsigned* Wlo = (unsigned*)(sm + OFF_WLO);
    unsigned* sA  = (unsigned*)(sm + OFF_SA);     // [split][16 rows][64 words]
    float* sf  = (float*)(sm + OFF_SF);           // [8][132] canonical fp32 state
    float* pre = (float*)(sm + OFF_PRE);          // [8][392] matvec results

    const int tid = threadIdx.x;
    const int lane = tid & 31, wid = tid >> 5;
    const int b0 = blockIdx.x * 8;
    const int d = tid & 127;
    const int r0 = (tid >> 7) * 4;
    const int ar = lane >> 2;            // 0..7 (row / n&7)
    const int q2 = (lane & 3) * 2;
    const int w8 = (wid << 3) + ar;      // B-frag n = w8 + 64*i

    // ---- init resident W (hi/lo, interleaved + rotated) ----
#pragma unroll 4
    for (int i = 0; i < 192; i++) {
        int idx = i * 256 + tid;         // 0..49151
        int g = idx >> 14;
        int k = (idx >> 7) & 127;
        int dd = idx & 127;
        const float* Wg = (g == 0) ? Wbu : ((g == 1) ? Wbr : Wbc);
        float v = Wg[k * DD + dd];
        __nv_bfloat16 h = __float2bfloat16(v);
        __nv_bfloat16 l = __float2bfloat16(v - __bfloat162float(h));
        int n = g * 128 + dd;
        int pos = n * 64 + ((word_of(k) + 8 * (n & 7)) & 63);
        ((__nv_bfloat16*)Whi)[pos * 2 + (k & 1)] = h;
        ((__nv_bfloat16*)Wlo)[pos * 2 + (k & 1)] = l;
    }
    // zero sA rows 8..15 (both splits) — mma M=16 padding
    for (int i = tid; i < 2 * 8 * 64; i += 256) {
        int sp = i >> 9, rw = i & 511;
        sA[sp * 1024 + (8 + (rw >> 6)) * 64 + (rw & 63)] = 0;
    }
    // load initial state (fp32 canonical + hi/lo splits)
    float bu = bau[d], brg = bar[d], bcg = bac[d];
#pragma unroll
    for (int jj = 0; jj < 4; jj++) {
        int r = r0 + jj;
        float v = state0[(size_t)(b0 + r) * DD + d];
        sf[r * 132 + d] = v;
        __nv_bfloat16 h = __float2bfloat16(v);
        __nv_bfloat16 l = __float2bfloat16(v - __bfloat162float(h));
        int pos = r * 64 + ((word_of(d) + 8 * r) & 63);
        ((__nv_bfloat16*)sA)[pos * 2 + (d & 1)] = h;
        ((__nv_bfloat16*)sA)[2048 + pos * 2 + (d & 1)] = l;
    }
    __syncthreads();

    for (int t = 0; t < TT; t++) {
        // early LDG: this step's x-projections + att/mask (hidden under matvec)
        float axu[4], axr[4], axc[4], av[4], mv[4];
#pragma unroll
        for (int jj = 0; jj < 4; jj++) {
            size_t row = (size_t)t * BB + b0 + r0 + jj;
            axu[jj] = g_Ax[row * NN + d];
            axr[jj] = g_Ax[row * NN + 128 + d];
            axc[jj] = g_Ax[row * NN + 256 + d];
            av[jj] = att[t * BB + b0 + r0 + jj];
            mv[jj] = mask[(size_t)(b0 + r0 + jj) * TT + t];
        }

        // ---- matvec: s @ Wb via 3-product split-bf16 mma ----
        float acc[6][4];
#pragma unroll
        for (int i = 0; i < 6; i++)
#pragma unroll
            for (int q = 0; q < 4; q++) acc[i][q] = 0.f;

#pragma unroll
        for (int ks = 0; ks < 8; ks++) {
            const int rot = (ks * 8 + q2 + 8 * ar) & 63;
            uint2 AH0 = *(const uint2*)(sA + (ar * 64 + rot));
            uint2 AH1 = *(const uint2*)(sA + ((ar + 8) * 64 + rot));
            uint2 AL0 = *(const uint2*)(sA + 1024 + (ar * 64 + rot));
            uint2 AL1 = *(const uint2*)(sA + 1024 + ((ar + 8) * 64 + rot));
            unsigned ah[4] = {AH0.x, AH1.x, AH0.y, AH1.y};
            unsigned al[4] = {AL0.x, AL1.x, AL0.y, AL1.y};
#pragma unroll
            for (int i = 0; i < 6; i++) {
                const int woff = (w8 + 64 * i) * 64 + rot;
                uint2 BH = *(const uint2*)(Whi + woff);
                uint2 BL = *(const uint2*)(Wlo + woff);
                unsigned bh[2] = {BH.x, BH.y};
                unsigned bl[2] = {BL.x, BL.y};
                mma16816(acc[i], ah, bh);
                mma16816(acc[i], al, bh);
                mma16816(acc[i], ah, bl);
            }
        }

        // store valid rows (c0,c1 = row ar, cols tilebase + q2)
#pragma unroll
        for (int i = 0; i < 6; i++) {
            int col = (wid << 3) + 64 * i + q2;
            *(float2*)(pre + ar * 392 + col) = make_float2(acc[i][0], acc[i][1]);
        }
        __syncthreads();   // B1: pre visible; sA reads done

        // ---- gates + state update ----
#pragma unroll
        for (int jj = 0; jj < 4; jj++) {
            int r = r0 + jj;
            float pu = pre[r * 392 + d];
            float pr = pre[r * 392 + 128 + d];
            float pc = pre[r * 392 + 256 + d];
            float u = fsig(axu[jj] + bu + pu);
            float rg = fsig(axr[jj] + brg + pr);
            float c = ftanh(axc[jj] + bcg + rg * pc);
            float so = sf[r * 132 + d];
            float sn = so + mv[jj] * (av[jj] * u * (c - so));
            sf[r * 132 + d] = sn;
            __nv_bfloat16 h = __float2bfloat16(sn);
            __nv_bfloat16 l = __float2bfloat16(sn - __bfloat162float(h));
            int pos = r * 64 + ((word_of(d) + 8 * r) & 63);
            ((__nv_bfloat16*)sA)[pos * 2 + (d & 1)] = h;
            ((__nv_bfloat16*)sA)[2048 + pos * 2 + (d & 1)] = l;
        }
        __syncthreads();   // B2: new state visible for next matvec
    }

#pragma unroll
    for (int jj = 0; jj < 4; jj++) {
        int r = r0 + jj;
        out[(size_t)(b0 + r) * DD + d] = sf[r * 132 + d];
    }
}

// ---------------- launch ----------------
extern "C" void kernel_launch(void* const* d_in, const int* in_sizes, int n_in,
                              void* d_out, int out_size) {
    const float* inputs = (const float*)d_in[0];   // [T,B,D]
    const float* state  = (const float*)d_in[1];   // [B,D]
    const float* att    = (const float*)d_in[2];   // [T,B,1]
    const float* mask   = (const float*)d_in[3];   // [B,T]
    // d_in[4] = max_len (compile-time TT)
    const float* Wau = (const float*)d_in[5];
    const float* bau = (const float*)d_in[6];
    const float* Wbu = (const float*)d_in[7];
    const float* War = (const float*)d_in[8];
    const float* bar = (const float*)d_in[9];
    const float* Wbr = (const float*)d_in[10];
    const float* Wac = (const float*)d_in[11];
    const float* bac = (const float*)d_in[12];
    const float* Wbc = (const float*)d_in[13];

    cudaFuncSetAttribute(xproj_tc, cudaFuncAttributeMaxDynamicSharedMemorySize, XTC_SMEM);
    cudaFuncSetAttribute(recur_tc, cudaFuncAttributeMaxDynamicSharedMemorySize, RC_SMEM);

    prep_w<<<3, 256>>>(Wau, War, Wac);
    prep_x<<<2048, 256>>>((const float4*)inputs);
    xproj_tc<<<3 * GCH, 256, XTC_SMEM>>>();
    recur_tc<<<BB / 8, 256, RC_SMEM>>>(state, att, mask, bau, bar, bac,
                                       Wbu, Wbr, Wbc, (float*)d_out);
}

// round 8
// speedup vs baseline: 2.2216x; 1.1430x over previous
#include <cuda_runtime.h>
#include <cuda_bf16.h>

#define TT 200
#define BB 1024
#define DD 128
#define NN 384        // 3 gates * 128
#define NCH 1600      // (TT*BB)/128 row-chunks
#define GCH 48        // chunk stride per gemm CTA (144 CTAs = 3 gates * 48)
#define XP 136        // padded k-length (bf16) for xproj smem tiles

// ---------------- device scratch (no runtime allocation allowed) ----------------
__device__ float g_Ax[(size_t)TT * BB * NN];                       // [row][n] row-major
__device__ __align__(16) __nv_bfloat16 g_Xhi[(size_t)TT * BB * DD];
__device__ __align__(16) __nv_bfloat16 g_Xlo[(size_t)TT * BB * DD];
__device__ __align__(16) __nv_bfloat16 g_Whi[3 * DD * DD];         // [gate][n][k]
__device__ __align__(16) __nv_bfloat16 g_Wlo[3 * DD * DD];

// ---------------- PTX helpers ----------------
static __device__ __forceinline__ void cp16(void* dst_sh, const void* src) {
    unsigned s = (unsigned)__cvta_generic_to_shared(dst_sh);
    asm volatile("cp.async.cg.shared.global [%0], [%1], 16;" :: "r"(s), "l"(src));
}
static __device__ __forceinline__ void cp_commit() { asm volatile("cp.async.commit_group;"); }
static __device__ __forceinline__ void cp_wait1() { asm volatile("cp.async.wait_group 1;"); }

// bf16 mma, fp32 accumulate, baseline PTX (compiles at compute_103)
static __device__ __forceinline__ void mma16816(float* d, const unsigned* a, const unsigned* b) {
    asm volatile(
        "mma.sync.aligned.m16n8k16.row.col.f32.bf16.bf16.f32 "
        "{%0,%1,%2,%3}, {%4,%5,%6,%7}, {%8,%9}, {%0,%1,%2,%3};"
        : "+f"(d[0]), "+f"(d[1]), "+f"(d[2]), "+f"(d[3])
        : "r"(a[0]), "r"(a[1]), "r"(a[2]), "r"(a[3]), "r"(b[0]), "r"(b[1]));
}

static __device__ __forceinline__ float fsig(float x) {
    return __fdividef(1.f, 1.f + __expf(-x));
}
static __device__ __forceinline__ float ftanh(float x) {
    float y = fminf(fmaxf(2.f * x, -30.f), 30.f);
    float e = __expf(y);
    return __fdividef(e - 1.f, e + 1.f);
}
static __device__ __forceinline__ unsigned pack2bf(__nv_bfloat16 a, __nv_bfloat16 b) {
    return (unsigned)__bfloat16_as_ushort(a) | ((unsigned)__bfloat16_as_ushort(b) << 16);
}

// k -> interleaved word index within a 64-word (128 bf16) row.
static __device__ __forceinline__ int word_of(int k) {
    int ks = k >> 4, r16 = k & 15;
    return ks * 8 + (((r16 & 7) >> 1) << 1) + (r16 >> 3);
}

// ==================== prep: X -> bf16 hi/lo (row-major) ====================
__global__ void prep_x(const float4* __restrict__ X4) {
    const size_t n4 = (size_t)TT * BB * DD / 4;
    for (size_t i = (size_t)blockIdx.x * blockDim.x + threadIdx.x; i < n4;
         i += (size_t)gridDim.x * blockDim.x) {
        float4 v = X4[i];
        __nv_bfloat16 hx = __float2bfloat16(v.x), hy = __float2bfloat16(v.y);
        __nv_bfloat16 hz = __float2bfloat16(v.z), hw = __float2bfloat16(v.w);
        uint2 h, l;
        h.x = pack2bf(hx, hy);
        h.y = pack2bf(hz, hw);
        l.x = pack2bf(__float2bfloat16(v.x - __bfloat162float(hx)),
                      __float2bfloat16(v.y - __bfloat162float(hy)));
        l.y = pack2bf(__float2bfloat16(v.z - __bfloat162float(hz)),
                      __float2bfloat16(v.w - __bfloat162float(hw)));
        ((uint2*)g_Xhi)[i] = h;
        ((uint2*)g_Xlo)[i] = l;
    }
}

// ==================== prep: Wa -> transposed [n][k] bf16 hi/lo ====================
__global__ void prep_w(const float* __restrict__ Wau, const float* __restrict__ War,
                       const float* __restrict__ Wac) {
    const int g = blockIdx.x;
    const float* W = (g == 0) ? Wau : ((g == 1) ? War : Wac);
    for (int idx = threadIdx.x; idx < DD * DD; idx += blockDim.x) {
        int n = idx >> 7, k = idx & 127;
        float v = W[k * DD + n];
        __nv_bfloat16 hi = __float2bfloat16(v);
        g_Whi[g * DD * DD + idx] = hi;
        g_Wlo[g * DD * DD + idx] = __float2bfloat16(v - __bfloat162float(hi));
    }
}

// ==================== phase 1 GEMM (mma.sync bf16, split-3): g_Ax = X @ Wg ====================
#define XTC_SMEM (6 * DD * XP * 2)   // 208896 bytes

static __device__ __forceinline__ void stageX(__nv_bfloat16* dst, int c, int tid) {
#pragma unroll
    for (int q = 0; q < 16; q++) {
        int id = q * 256 + tid;
        int sp = id >> 11, rr = (id >> 4) & 127, sg = id & 15;
        const __nv_bfloat16* src = (sp ? g_Xlo : g_Xhi) + (size_t)c * (DD * DD) + rr * DD + sg * 8;
        cp16(dst + sp * (DD * XP) + rr * XP + sg * 8, src);
    }
}

__global__ __launch_bounds__(256, 1) void xproj_tc() {
    extern __shared__ __align__(16) __nv_bfloat16 smp[];
    __nv_bfloat16* Xb0 = smp;
    __nv_bfloat16* Xb1 = smp + 2 * DD * XP;
    __nv_bfloat16* Wp  = smp + 4 * DD * XP;

    const int tid = threadIdx.x;
    const int gate = blockIdx.x / GCH;
    const int part = blockIdx.x % GCH;
    const int wid = tid >> 5, lane = tid & 31;
    const int g = lane >> 2, tg = lane & 3;
    const int wm = wid >> 2, wn = wid & 3;

#pragma unroll
    for (int q = 0; q < 16; q++) {
        int id = q * 256 + tid;
        int sp = id >> 11, rr = (id >> 4) & 127, sg = id & 15;
        const __nv_bfloat16* src = (sp ? g_Wlo : g_Whi) + gate * DD * DD + rr * DD + sg * 8;
        cp16(Wp + sp * (DD * XP) + rr * XP + sg * 8, src);
    }
    stageX(Xb0, part, tid);
    cp_commit();

    int buf = 0;
    for (int c = part; c < NCH; c += GCH) {
        const int cn = c + GCH;
        if (cn < NCH) stageX(buf ? Xb0 : Xb1, cn, tid);
        cp_commit();
        cp_wait1();
        __syncthreads();

        const __nv_bfloat16* Xhi_s = buf ? Xb1 : Xb0;
        const __nv_bfloat16* Xlo_s = Xhi_s + DD * XP;
        const __nv_bfloat16* Whi_s = Wp;
        const __nv_bfloat16* Wlo_s = Wp + DD * XP;

        float acc[4][4][4];
#pragma unroll
        for (int mt = 0; mt < 4; mt++)
#pragma unroll
            for (int nt = 0; nt < 4; nt++)
#pragma unroll
                for (int q = 0; q < 4; q++) acc[mt][nt][q] = 0.f;

        const int arow = wm * 64 + g;
        const int bcol = wn * 32 + g;

#pragma unroll
        for (int ks = 0; ks < 8; ks++) {
            const int k0 = ks * 16 + 2 * tg;
            unsigned ah[4][4], bh[4][2];
#pragma unroll
            for (int mt = 0; mt < 4; mt++) {
                const __nv_bfloat16* pa = Xhi_s + (arow + mt * 16) * XP + k0;
                ah[mt][0] = *(const unsigned*)pa;
                ah[mt][1] = *(const unsigned*)(pa + 8 * XP);
                ah[mt][2] = *(const unsigned*)(pa + 8);
                ah[mt][3] = *(const unsigned*)(pa + 8 * XP + 8);
            }
#pragma unroll
            for (int nt = 0; nt < 4; nt++) {
                const __nv_bfloat16* pb = Whi_s + (bcol + nt * 8) * XP + k0;
                bh[nt][0] = *(const unsigned*)pb;
                bh[nt][1] = *(const unsigned*)(pb + 8);
            }
#pragma unroll
            for (int mt = 0; mt < 4; mt++)
#pragma unroll
                for (int nt = 0; nt < 4; nt++) mma16816(acc[mt][nt], ah[mt], bh[nt]);
            {
                unsigned al[4][4];
#pragma unroll
                for (int mt = 0; mt < 4; mt++) {
                    const __nv_bfloat16* pa = Xlo_s + (arow + mt * 16) * XP + k0;
                    al[mt][0] = *(const unsigned*)pa;
                    al[mt][1] = *(const unsigned*)(pa + 8 * XP);
                    al[mt][2] = *(const unsigned*)(pa + 8);
                    al[mt][3] = *(const unsigned*)(pa + 8 * XP + 8);
                }
#pragma unroll
                for (int mt = 0; mt < 4; mt++)
#pragma unroll
                    for (int nt = 0; nt < 4; nt++) mma16816(acc[mt][nt], al[mt], bh[nt]);
            }
            {
                unsigned bl[4][2];
#pragma unroll
                for (int nt = 0; nt < 4; nt++) {
                    const __nv_bfloat16* pb = Wlo_s + (bcol + nt * 8) * XP + k0;
                    bl[nt][0] = *(const unsigned*)pb;
                    bl[nt][1] = *(const unsigned*)(pb + 8);
                }
#pragma unroll
                for (int mt = 0; mt < 4; mt++)
#pragma unroll
                    for (int nt = 0; nt < 4; nt++) mma16816(acc[mt][nt], ah[mt], bl[nt]);
            }
        }

        const size_t rbase = (size_t)c * 128;
#pragma unroll
        for (int mt = 0; mt < 4; mt++) {
#pragma unroll
            for (int nt = 0; nt < 4; nt++) {
                size_t r1 = rbase + wm * 64 + mt * 16 + g;
                int col = gate * 128 + wn * 32 + nt * 8 + 2 * tg;
                *(float2*)&g_Ax[r1 * NN + col] = make_float2(acc[mt][nt][0], acc[mt][nt][1]);
                *(float2*)&g_Ax[(r1 + 8) * NN + col] = make_float2(acc[mt][nt][2], acc[mt][nt][3]);
            }
        }
        __syncthreads();
        buf ^= 1;
    }
}

// ==================== phase 2: recurrence on mma.sync, 512 threads ====================
// 128 CTAs x 8 batch rows, 16 warps. Warp w owns n-cols {w*8 + 128*i, i=0..2}.
// B_hi fragments in registers; B_lo via LDS; 2 accumulators per tile.
#define OFF_WLO 98304
#define OFF_SA  196608
#define OFF_SF  204800
#define OFF_PRE 209024
#define RC_SMEM 221568

__global__ __launch_bounds__(512, 1)
void recur_tc(const float* __restrict__ state0,
              const float* __restrict__ att,    // [T,B,1]
              const float* __restrict__ mask,   // [B,T]
              const float* __restrict__ bau, const float* __restrict__ bar,
              const float* __restrict__ bac,
              const float* __restrict__ Wbu, const float* __restrict__ Wbr,
              const float* __restrict__ Wbc,
              float* __restrict__ out) {
    extern __shared__ char sm[];
    unsigned* Whi = (unsigned*)sm;
    unsigned* Wlo = (unsigned*)(sm + OFF_WLO);
    unsigned* sA  = (unsigned*)(sm + OFF_SA);     // [split][16 rows][64 words]
    float* sf  = (float*)(sm + OFF_SF);           // [8][132] canonical fp32 state
    float* pre = (float*)(sm + OFF_PRE);          // [8][392] matvec results

    const int tid = threadIdx.x;
    const int lane = tid & 31, wid = tid >> 5;
    const int b0 = blockIdx.x * 8;
    const int d = tid & 127;
    const int r0 = tid >> 7;             // 0..3 (owns rows r0, r0+4)
    const int ar = lane >> 2;            // 0..7
    const int q2 = (lane & 3) * 2;
    const int w8 = (wid << 3) + ar;      // B-frag n = w8 + 128*i

    // ---- init resident W (hi/lo, interleaved + rotated) ----
#pragma unroll 4
    for (int i = 0; i < 96; i++) {
        int idx = i * 512 + tid;         // 0..49151
        int g = idx >> 14;
        int k = (idx >> 7) & 127;
        int dd = idx & 127;
        const float* Wg = (g == 0) ? Wbu : ((g == 1) ? Wbr : Wbc);
        float v = Wg[k * DD + dd];
        __nv_bfloat16 h = __float2bfloat16(v);
        __nv_bfloat16 l = __float2bfloat16(v - __bfloat162float(h));
        int n = g * 128 + dd;
        int pos = n * 64 + ((word_of(k) + 8 * (n & 7)) & 63);
        ((__nv_bfloat16*)Whi)[pos * 2 + (k & 1)] = h;
        ((__nv_bfloat16*)Wlo)[pos * 2 + (k & 1)] = l;
    }
    // zero sA rows 8..15 (both splits)
    for (int i = tid; i < 2 * 8 * 64; i += 512) {
        int sp = i >> 9, rw = i & 511;
        sA[sp * 1024 + (8 + (rw >> 6)) * 64 + (rw & 63)] = 0;
    }
    // load initial state (fp32 canonical + hi/lo splits): rows r0, r0+4
    float bu = bau[d], brg = bar[d], bcg = bac[d];
#pragma unroll
    for (int jj = 0; jj < 2; jj++) {
        int r = r0 + 4 * jj;
        float v = state0[(size_t)(b0 + r) * DD + d];
        sf[r * 132 + d] = v;
        __nv_bfloat16 h = __float2bfloat16(v);
        __nv_bfloat16 l = __float2bfloat16(v - __bfloat162float(h));
        int pos = r * 64 + ((word_of(d) + 8 * r) & 63);
        ((__nv_bfloat16*)sA)[pos * 2 + (d & 1)] = h;
        ((__nv_bfloat16*)sA)[2048 + pos * 2 + (d & 1)] = l;
    }
    __syncthreads();

    // ---- preload B_hi fragments into registers (step-invariant) ----
    unsigned bhr[3][8][2];
#pragma unroll
    for (int i = 0; i < 3; i++) {
#pragma unroll
        for (int ks = 0; ks < 8; ks++) {
            const int rot = (ks * 8 + q2 + 8 * ar) & 63;
            uint2 BH = *(const uint2*)(Whi + (w8 + 128 * i) * 64 + rot);
            bhr[i][ks][0] = BH.x;
            bhr[i][ks][1] = BH.y;
        }
    }

    for (int t = 0; t < TT; t++) {
        // early LDG: this step's x-projections + att/mask (hidden under matvec)
        float axu[2], axr[2], axc[2], av[2], mv[2];
#pragma unroll
        for (int jj = 0; jj < 2; jj++) {
            int r = r0 + 4 * jj;
            size_t row = (size_t)t * BB + b0 + r;
            axu[jj] = g_Ax[row * NN + d];
            axr[jj] = g_Ax[row * NN + 128 + d];
            axc[jj] = g_Ax[row * NN + 256 + d];
            av[jj] = att[t * BB + b0 + r];
            mv[jj] = mask[(size_t)(b0 + r) * TT + t];
        }

        // ---- matvec: s @ Wb, 3-product split-bf16, 2 accumulators per tile ----
        float accA[3][4], accB[3][4];
#pragma unroll
        for (int i = 0; i < 3; i++)
#pragma unroll
            for (int q = 0; q < 4; q++) { accA[i][q] = 0.f; accB[i][q] = 0.f; }

#pragma unroll
        for (int ks = 0; ks < 8; ks++) {
            const int rot = (ks * 8 + q2 + 8 * ar) & 63;
            uint2 AH0 = *(const uint2*)(sA + (ar * 64 + rot));
            uint2 AH1 = *(const uint2*)(sA + ((ar + 8) * 64 + rot));
            uint2 AL0 = *(const uint2*)(sA + 1024 + (ar * 64 + rot));
            uint2 AL1 = *(const uint2*)(sA + 1024 + ((ar + 8) * 64 + rot));
            unsigned ah[4] = {AH0.x, AH1.x, AH0.y, AH1.y};
            unsigned al[4] = {AL0.x, AL1.x, AL0.y, AL1.y};
#pragma unroll
            for (int i = 0; i < 3; i++) {
                uint2 BL = *(const uint2*)(Wlo + (w8 + 128 * i) * 64 + rot);
                unsigned bl[2] = {BL.x, BL.y};
                mma16816(accA[i], ah, bhr[i][ks]);
                mma16816(accB[i], al, bhr[i][ks]);
                mma16816(accB[i], ah, bl);
            }
        }

        // store row ar, cols wid*8 + 128*i + q2
#pragma unroll
        for (int i = 0; i < 3; i++) {
            int col = (wid << 3) + 128 * i + q2;
            *(float2*)(pre + ar * 392 + col) =
                make_float2(accA[i][0] + accB[i][0], accA[i][1] + accB[i][1]);
        }
        __syncthreads();   // B1: pre visible; sA reads done

        // ---- gates + state update (2 items/thread: rows r0, r0+4; same d) ----
#pragma unroll
        for (int jj = 0; jj < 2; jj++) {
            int r = r0 + 4 * jj;
            float pu = pre[r * 392 + d];
            float pr = pre[r * 392 + 128 + d];
            float pc = pre[r * 392 + 256 + d];
            float u = fsig(axu[jj] + bu + pu);
            float rg = fsig(axr[jj] + brg + pr);
            float c = ftanh(axc[jj] + bcg + rg * pc);
            float so = sf[r * 132 + d];
            float sn = so + mv[jj] * (av[jj] * u * (c - so));
            sf[r * 132 + d] = sn;
            __nv_bfloat16 h = __float2bfloat16(sn);
            __nv_bfloat16 l = __float2bfloat16(sn - __bfloat162float(h));
            int pos = r * 64 + ((word_of(d) + 8 * r) & 63);
            ((__nv_bfloat16*)sA)[pos * 2 + (d & 1)] = h;
            ((__nv_bfloat16*)sA)[2048 + pos * 2 + (d & 1)] = l;
        }
        __syncthreads();   // B2: new state visible for next matvec
    }

#pragma unroll
    for (int jj = 0; jj < 2; jj++) {
        int r = r0 + 4 * jj;
        out[(size_t)(b0 + r) * DD + d] = sf[r * 132 + d];
    }
}

// ---------------- launch ----------------
extern "C" void kernel_launch(void* const* d_in, const int* in_sizes, int n_in,
                              void* d_out, int out_size) {
    const float* inputs = (const float*)d_in[0];   // [T,B,D]
    const float* state  = (const float*)d_in[1];   // [B,D]
    const float* att    = (const float*)d_in[2];   // [T,B,1]
    const float* mask   = (const float*)d_in[3];   // [B,T]
    // d_in[4] = max_len (compile-time TT)
    const float* Wau = (const float*)d_in[5];
    const float* bau = (const float*)d_in[6];
    const float* Wbu = (const float*)d_in[7];
    const float* War = (const float*)d_in[8];
    const float* bar = (const float*)d_in[9];
    const float* Wbr = (const float*)d_in[10];
    const float* Wac = (const float*)d_in[11];
    const float* bac = (const float*)d_in[12];
    const float* Wbc = (const float*)d_in[13];

    cudaFuncSetAttribute(xproj_tc, cudaFuncAttributeMaxDynamicSharedMemorySize, XTC_SMEM);
    cudaFuncSetAttribute(recur_tc, cudaFuncAttributeMaxDynamicSharedMemorySize, RC_SMEM);

    prep_w<<<3, 256>>>(Wau, War, Wac);
    prep_x<<<2048, 256>>>((const float4*)inputs);
    xproj_tc<<<3 * GCH, 256, XTC_SMEM>>>();
    recur_tc<<<BB / 8, 512, RC_SMEM>>>(state, att, mask, bau, bar, bac,
                                       Wbu, Wbr, Wbc, (float*)d_out);
}